// round 2
// baseline (speedup 1.0000x reference)
#include <cuda_runtime.h>
#include <cmath>
#include <algorithm>

#ifndef M_PI
#define M_PI 3.14159265358979323846
#endif

// ---------------- constants ----------------
#define kB    2
#define kL    196
#define kE    768
#define kDIM  3072
#define kDIN  6144
#define kDIN2 12288
#define kDTR  192
#define kDST  16
#define kM    392            // kB*kL
#define kXPN  224            // kDTR + 2*kDST

// ---------------- device scratch (static, allowed) ----------------
__device__ float g_xe  [kM * kE];
__device__ float g_xm  [kM * kDIM];
__device__ float g_xln [kM * kDIM];
__device__ float g_xr  [kM * kDIN2];
__device__ float g_xs  [kM * kDIN];
__device__ float g_dbl [kM * kXPN];
__device__ float g_dt  [kM * kDIN];
__device__ float g_y   [kM * kDIN];
__device__ float g_part[4 * kM * kDIM];   // split-K partials (4*392*3072)
__device__ float g_proj[kM * kE];

struct Perms { int sp[kL]; int ra[kL]; int bd[kL]; };

// ---------------- helpers ----------------
__device__ __forceinline__ float softplusf(float v) {
    return fmaxf(v, 0.f) + log1pf(expf(-fabsf(v)));
}
__device__ __forceinline__ float siluf(float v) {
    return v / (1.f + expf(-v));
}

__device__ __forceinline__ float block_reduce_256(float v, float* red) {
    #pragma unroll
    for (int o = 16; o; o >>= 1) v += __shfl_xor_sync(0xffffffffu, v, o);
    if ((threadIdx.x & 31) == 0) red[threadIdx.x >> 5] = v;
    __syncthreads();
    float r = 0.f;
    if (threadIdx.x < 8) {
        r = red[threadIdx.x];
        #pragma unroll
        for (int o = 4; o; o >>= 1) r += __shfl_xor_sync(0xffu, r, o);
        if (threadIdx.x == 0) red[0] = r;
    }
    __syncthreads();
    r = red[0];
    __syncthreads();   // red reusable afterwards
    return r;
}

// ---------------- patch embedding ----------------
__global__ __launch_bounds__(256) void patch_embed_kernel(
    const float* __restrict__ x, const float* __restrict__ pw,
    const float* __restrict__ pb, const float* __restrict__ pos,
    const float* __restrict__ af, const float* __restrict__ aw,
    const float* __restrict__ ab, float* __restrict__ xe)
{
    __shared__ float patch[768];
    int blk = blockIdx.x;
    int b = blk / kL, l = blk % kL;
    int h = l / 14, w = l % 14;
    int tid = threadIdx.x;
    for (int k = tid; k < 768; k += 256) {
        int c = k >> 8, rem = k & 255, i = rem >> 4, j = rem & 15;
        patch[k] = x[(((size_t)b * 3 + c) * 224 + (h * 16 + i)) * 224 + (w * 16 + j)];
    }
    __syncthreads();
    float f0 = af[b*5+0], f1 = af[b*5+1], f2 = af[b*5+2], f3 = af[b*5+3], f4 = af[b*5+4];
    for (int e = tid; e < 768; e += 256) {
        float acc = pb[e];
        const float* wr = pw + (size_t)e * 768;
        #pragma unroll 8
        for (int k = 0; k < 768; k++) acc += patch[k] * wr[k];
        acc += pos[(size_t)l * 768 + e] + ab[e]
             + f0*aw[e*5+0] + f1*aw[e*5+1] + f2*aw[e*5+2] + f3*aw[e*5+3] + f4*aw[e*5+4];
        xe[((size_t)b * kL + l) * 768 + e] = acc;
    }
}

// ---------------- permutation concat ----------------
__global__ __launch_bounds__(256) void gather_kernel(
    const float* __restrict__ xe, float* __restrict__ xm, Perms P)
{
    int i = blockIdx.x * 256 + threadIdx.x;
    if (i >= kM * kDIM) return;
    int col = i % kDIM;
    int row = i / kDIM;
    int b = row / kL, t = row % kL;
    int c = col / kE, e = col % kE;
    int ts = (c == 0) ? P.sp[t] : (c == 1) ? P.ra[t] : (c == 2) ? P.bd[t] : t;
    xm[i] = xe[((size_t)(b * kL + ts)) * kE + e];
}

// ---------------- layernorm over rows ----------------
__global__ __launch_bounds__(256) void layernorm_rows(
    const float* __restrict__ in, float* __restrict__ out,
    const float* __restrict__ w, const float* __restrict__ b, int C)
{
    __shared__ float red[8];
    int row = blockIdx.x, tid = threadIdx.x;
    const float* xr = in + (size_t)row * C;
    float v[12];
    int cnt = C >> 8;            // C/256  (12 for 3072, 3 for 768)
    float s = 0.f;
    for (int i = 0; i < cnt; i++) { v[i] = xr[tid + (i << 8)]; s += v[i]; }
    float mean = block_reduce_256(s, red) / (float)C;
    float q = 0.f;
    for (int i = 0; i < cnt; i++) { float d = v[i] - mean; q += d * d; }
    float var = block_reduce_256(q, red) / (float)C;
    float rs = rsqrtf(var + 1e-5f);
    float* o = out + (size_t)row * C;
    for (int i = 0; i < cnt; i++) {
        int c = tid + (i << 8);
        o[c] = (v[i] - mean) * rs * w[c] + b[c];
    }
}

// ---------------- generic SGEMM: C = A(MxK, lda) @ W(NxK)^T, split-K via blockIdx.z ----------------
// epi: 0 none, 1 +bias[n], 2 softplus(v + bias[n])   (epi only valid when gridDim.z == 1)
__global__ __launch_bounds__(256) void sgemm_nt(
    const float* __restrict__ A, int lda,
    const float* __restrict__ W,
    float* __restrict__ C,
    int M, int N, int K, int kChunk,
    const float* __restrict__ bias, int epi)
{
    __shared__ float As[16][132];
    __shared__ float Bs[16][132];
    const int z  = blockIdx.z;
    const int k0 = z * kChunk;
    int kLen = K - k0; if (kLen > kChunk) kLen = kChunk;
    const int m0 = blockIdx.y * 128;
    const int n0 = blockIdx.x * 128;
    float* Cz = C + (size_t)z * M * N;
    const int tid = threadIdx.x;
    const int tx = tid & 15, ty = tid >> 4;
    float acc[8][8];
    #pragma unroll
    for (int i = 0; i < 8; i++)
        #pragma unroll
        for (int j = 0; j < 8; j++) acc[i][j] = 0.f;

    const int lr = tid >> 2;            // 0..63
    const int lc = (tid & 3) << 2;      // 0,4,8,12

    for (int kt = 0; kt < kLen; kt += 16) {
        #pragma unroll
        for (int hsel = 0; hsel < 2; hsel++) {
            int row = lr + (hsel << 6);
            float4 va = make_float4(0.f, 0.f, 0.f, 0.f);
            int gm = m0 + row;
            if (gm < M) va = *reinterpret_cast<const float4*>(&A[(size_t)gm * lda + k0 + kt + lc]);
            As[lc+0][row] = va.x; As[lc+1][row] = va.y; As[lc+2][row] = va.z; As[lc+3][row] = va.w;
            float4 vb = make_float4(0.f, 0.f, 0.f, 0.f);
            int gn = n0 + row;
            if (gn < N) vb = *reinterpret_cast<const float4*>(&W[(size_t)gn * K + k0 + kt + lc]);
            Bs[lc+0][row] = vb.x; Bs[lc+1][row] = vb.y; Bs[lc+2][row] = vb.z; Bs[lc+3][row] = vb.w;
        }
        __syncthreads();
        #pragma unroll
        for (int kk = 0; kk < 16; kk++) {
            float a[8], b[8];
            *reinterpret_cast<float4*>(&a[0]) = *reinterpret_cast<const float4*>(&As[kk][ty * 8]);
            *reinterpret_cast<float4*>(&a[4]) = *reinterpret_cast<const float4*>(&As[kk][ty * 8 + 4]);
            *reinterpret_cast<float4*>(&b[0]) = *reinterpret_cast<const float4*>(&Bs[kk][tx * 8]);
            *reinterpret_cast<float4*>(&b[4]) = *reinterpret_cast<const float4*>(&Bs[kk][tx * 8 + 4]);
            #pragma unroll
            for (int i = 0; i < 8; i++)
                #pragma unroll
                for (int j = 0; j < 8; j++)
                    acc[i][j] += a[i] * b[j];
        }
        __syncthreads();
    }

    #pragma unroll
    for (int i = 0; i < 8; i++) {
        int gm = m0 + ty * 8 + i;
        if (gm >= M) continue;
        #pragma unroll
        for (int j = 0; j < 8; j++) {
            int gn = n0 + tx * 8 + j;
            if (gn >= N) continue;
            float v = acc[i][j];
            if (epi == 1)      v += bias[gn];
            else if (epi == 2) v = softplusf(v + bias[gn]);
            Cz[(size_t)gm * N + gn] = v;
        }
    }
}

// ---------------- split-K reduce (+epilogue) ----------------
// epi: 0 none, 1 +extra[i % N] (bias), 2 +extra[i] (residual; out may alias extra)
__global__ __launch_bounds__(256) void reduce_splitk(
    const float* __restrict__ part, float* __restrict__ out,
    int MN, int N, int S, const float* __restrict__ extra, int epi)
{
    int i = blockIdx.x * 256 + threadIdx.x;
    if (i >= MN) return;
    float s = 0.f;
    for (int zz = 0; zz < S; zz++) s += part[(size_t)zz * MN + i];
    if (epi == 1)      s += extra[i % N];
    else if (epi == 2) s += extra[i];
    out[i] = s;
}

// ---------------- causal depthwise conv(4) + SiLU ----------------
__global__ __launch_bounds__(256) void conv_silu_kernel(
    const float* __restrict__ xr, const float* __restrict__ cw,
    const float* __restrict__ cb, float* __restrict__ xs)
{
    int i = blockIdx.x * 256 + threadIdx.x;
    if (i >= kM * kDIN) return;
    int d = i % kDIN;
    int row = i / kDIN;
    int b = row / kL, t = row % kL;
    float acc = cb[d];
    #pragma unroll
    for (int j = 0; j < 4; j++) {
        int tt = t - 3 + j;
        if (tt >= 0)
            acc += cw[d * 4 + j] * xr[((size_t)(b * kL + tt)) * kDIN2 + d];
    }
    xs[i] = siluf(acc);
}

// ---------------- selective-scan (sequential over L), + D skip + SiLU gate ----------------
__global__ __launch_bounds__(128) void scan_kernel(
    const float* __restrict__ dt, const float* __restrict__ dbl,
    const float* __restrict__ xs, const float* __restrict__ xr,
    const float* __restrict__ alog, const float* __restrict__ dpar,
    float* __restrict__ y)
{
    int idx = blockIdx.x * 128 + threadIdx.x;      // 0 .. kB*kDIN-1
    int b = idx / kDIN, d = idx % kDIN;
    float A[kDST];
    #pragma unroll
    for (int n = 0; n < kDST; n++) A[n] = -expf(alog[(size_t)d * kDST + n]);
    float Dv = dpar[d];
    float st[kDST];
    #pragma unroll
    for (int n = 0; n < kDST; n++) st[n] = 0.f;

    for (int t = 0; t < kL; t++) {
        size_t row = (size_t)b * kL + t;
        float dtv = dt[row * kDIN + d];
        float xv  = xs[row * kDIN + d];
        const float* bc = dbl + row * kXPN + kDTR;   // [B(16) | C(16)]
        float dtx = dtv * xv;
        float yv = 0.f;
        #pragma unroll
        for (int n = 0; n < kDST; n++) {
            st[n] = st[n] * expf(dtv * A[n]) + dtx * __ldg(&bc[n]);
            yv += st[n] * __ldg(&bc[kDST + n]);
        }
        float r = xr[row * kDIN2 + kDIN + d];        // res half
        y[row * kDIN + d] = (yv + xv * Dv) * siluf(r);
    }
}

// ---------------- final token mean ----------------
__global__ void final_mean_kernel(const float* __restrict__ xp, float* __restrict__ out)
{
    int i = blockIdx.x * 256 + threadIdx.x;
    if (i >= kB * kE) return;
    int b = i / kE, e = i % kE;
    float s = 0.f;
    for (int t = 0; t < kL; t++) s += xp[((size_t)b * kL + t) * kE + e];
    out[i] = s * (1.0f / 196.0f);
}

// ---------------- host: permutation orders (bit-exact replica of reference Python) ----------------
static void compute_perms(Perms& P)
{
    const int Hh = 14, Ww = 14, ch = 7, cw = 7;
    // spiral
    {
        bool seen[kL] = {false};
        int no = 0;
        for (int r = 0; r < 14; r++) {
            int n = (2 * r > 8) ? 2 * r : 8;
            double step = (2.0 * M_PI) / (double)n;   // numpy linspace endpoint=False
            for (int k = 0; k < n; k++) {
                double ang = (double)k * step;
                int h = (int)((double)ch + (double)r * cos(ang));  // int() truncates toward 0
                int w = (int)((double)cw + (double)r * sin(ang));
                if (h >= 0 && h < Hh && w >= 0 && w < Ww) {
                    int i = h * Ww + w;
                    if (!seen[i]) { seen[i] = true; P.sp[no++] = i; }
                }
            }
        }
        for (int i = 0; i < kL; i++) if (!seen[i]) P.sp[no++] = i;  // sorted remainder
    }
    // radial: sort by (-d, a), stable
    {
        struct Item { double d, a; int i; };
        Item items[kL];
        int c = 0;
        for (int h = 0; h < Hh; h++)
            for (int w = 0; w < Ww; w++) {
                double dh = h - ch, dw = w - cw;
                items[c].d = sqrt(dh * dh + dw * dw);
                items[c].a = atan2(dh, dw);
                items[c].i = h * Ww + w;
                c++;
            }
        std::stable_sort(items, items + kL, [](const Item& x, const Item& y) {
            if (x.d != y.d) return x.d > y.d;
            return x.a < y.a;
        });
        for (int i = 0; i < kL; i++) P.ra[i] = items[i].i;
    }
    // boundary
    {
        int nb = 0;
        for (int h = 0; h < Hh; h++)
            for (int w = 0; w < Ww; w++)
                if (h == 0 || h == Hh - 1 || w == 0 || w == Ww - 1)
                    P.bd[nb++] = h * Ww + w;
        for (int h = 0; h < Hh; h++)
            for (int w = 0; w < Ww; w++)
                if (!(h == 0 || h == Hh - 1 || w == 0 || w == Ww - 1))
                    P.bd[nb++] = h * Ww + w;
    }
}

// ---------------- launch ----------------
extern "C" void kernel_launch(void* const* d_in, const int* in_sizes, int n_in,
                              void* d_out, int out_size)
{
    (void)n_in; (void)out_size;
    const float* x       = (const float*)d_in[0];
    const float* abf     = (const float*)d_in[1];
    const float* patch_w = (const float*)d_in[2];
    const float* patch_b = (const float*)d_in[3];
    const float* pos     = (const float*)d_in[4];
    const float* abw     = (const float*)d_in[5];
    const float* abb     = (const float*)d_in[6];
    const float* ln_w    = (const float*)d_in[7];
    const float* ln_b    = (const float*)d_in[8];
    const float* inw     = (const float*)d_in[9];
    const float* convw   = (const float*)d_in[10];
    const float* convb   = (const float*)d_in[11];
    const float* xpw     = (const float*)d_in[12];
    const float* dtw     = (const float*)d_in[13];
    const float *dtb, *alog, *dpar, *outw, *projw, *projb, *normw, *normb;
    if (in_sizes[14] == 2 * kDIN) {
        // reference() signature order: dt_proj_b at index 14
        dtb   = (const float*)d_in[14]; alog  = (const float*)d_in[15];
        dpar  = (const float*)d_in[16]; outw  = (const float*)d_in[17];
        projw = (const float*)d_in[18]; projb = (const float*)d_in[19];
        normw = (const float*)d_in[20]; normb = (const float*)d_in[21];
    } else {
        // setup_inputs() dict order: dt_proj_b appended last
        alog  = (const float*)d_in[14]; dpar  = (const float*)d_in[15];
        outw  = (const float*)d_in[16]; projw = (const float*)d_in[17];
        projb = (const float*)d_in[18]; normw = (const float*)d_in[19];
        normb = (const float*)d_in[20]; dtb   = (const float*)d_in[21];
    }

    float *xe, *xm, *xln, *xr, *xs, *dbl, *dt, *y, *part, *proj;
    cudaGetSymbolAddress((void**)&xe,   g_xe);
    cudaGetSymbolAddress((void**)&xm,   g_xm);
    cudaGetSymbolAddress((void**)&xln,  g_xln);
    cudaGetSymbolAddress((void**)&xr,   g_xr);
    cudaGetSymbolAddress((void**)&xs,   g_xs);
    cudaGetSymbolAddress((void**)&dbl,  g_dbl);
    cudaGetSymbolAddress((void**)&dt,   g_dt);
    cudaGetSymbolAddress((void**)&y,    g_y);
    cudaGetSymbolAddress((void**)&part, g_part);
    cudaGetSymbolAddress((void**)&proj, g_proj);

    auto gemm = [&](const float* A, int lda, const float* W, float* C,
                    int M, int N, int K, int S, const float* bias, int epi) {
        int kChunk = K / S;     // all splits chosen so K/S is a multiple of 16
        dim3 grid((N + 127) / 128, (M + 127) / 128, S);
        sgemm_nt<<<grid, 256>>>(A, lda, W, C, M, N, K, kChunk, bias, epi);
    };

    // --- patch embed + permutation concat ---
    patch_embed_kernel<<<kM, 256>>>(x, patch_w, patch_b, pos, abf, abw, abb, xe);
    Perms P;
    compute_perms(P);
    gather_kernel<<<(kM * kDIM) / 256, 256>>>(xe, xm, P);

    // --- mamba layers ---
    for (int l = 0; l < 2; l++) {
        layernorm_rows<<<kM, 256>>>(xm, xln, ln_w + l * kDIM, ln_b + l * kDIM, kDIM);
        // in_proj: (392,3072) @ (12288,3072)^T
        gemm(xln, kDIM, inw + (size_t)l * kDIN2 * kDIM, xr, kM, kDIN2, kDIM, 1, nullptr, 0);
        // depthwise conv + silu
        conv_silu_kernel<<<(kM * kDIN) / 256, 256>>>(xr, convw + (size_t)l * kDIN * 4,
                                                     convb + l * kDIN, xs);
        // x_proj: (392,6144) @ (224,6144)^T, split-K 16
        gemm(xs, kDIN, xpw + (size_t)l * kXPN * kDIN, part, kM, kXPN, kDIN, 16, nullptr, 0);
        reduce_splitk<<<(kM * kXPN + 255) / 256, 256>>>(part, dbl, kM * kXPN, kXPN, 16, nullptr, 0);
        // dt_proj + softplus: (392,192) @ (6144,192)^T
        gemm(dbl, kXPN, dtw + (size_t)l * kDIN * kDTR, dt, kM, kDIN, kDTR, 1, dtb + l * kDIN, 2);
        // selective scan + gating
        scan_kernel<<<(kB * kDIN) / 128, 128>>>(dt, dbl, xs, xr,
                                                alog + (size_t)l * kDIN * kDST,
                                                dpar + l * kDIN, y);
        // out_proj + residual: (392,6144) @ (3072,6144)^T, split-K 4
        gemm(y, kDIN, outw + (size_t)l * kDIM * kDIN, part, kM, kDIM, kDIN, 4, nullptr, 0);
        reduce_splitk<<<(kM * kDIM + 255) / 256, 256>>>(part, xm, kM * kDIM, kDIM, 4, xm, 2);
    }

    // --- final projection + LN + mean ---
    gemm(xm, kDIM, projw, part, kM, kE, kDIM, 8, nullptr, 0);
    reduce_splitk<<<(kM * kE + 255) / 256, 256>>>(part, proj, kM * kE, kE, 8, projb, 1);
    layernorm_rows<<<kM, 256>>>(proj, proj, normw, normb, kE);
    final_mean_kernel<<<(kB * kE + 255) / 256, 256>>>(proj, (float*)d_out);
}

// round 8
// speedup vs baseline: 1.4001x; 1.4001x over previous
#include <cuda_runtime.h>
#include <cstdint>
#include <cmath>
#include <algorithm>

#ifndef M_PI
#define M_PI 3.14159265358979323846
#endif

// ---------------- constants ----------------
#define kB    2
#define kL    196
#define kE    768
#define kDIM  3072
#define kDIN  6144
#define kDIN2 12288
#define kDTR  192
#define kDST  16
#define kM    392            // kB*kL
#define kXPN  224            // kDTR + 2*kDST

// ---------------- device scratch ----------------
__device__ float g_xe  [kM * kE];
__device__ float g_xm  [kM * kDIM];
__device__ float g_xln [kM * kDIM];
__device__ float g_xr  [kM * kDIN2];
__device__ float g_xs  [kM * kDIN];
__device__ float g_dbl [kM * kXPN];
__device__ float g_dt  [kM * kDIN];
__device__ float g_y   [kM * kDIN];
__device__ float g_part[16 * kM * kXPN > 6 * kM * kE ? 16 * kM * kXPN : 6 * kM * kE > 2 * kM * kDIM ? 6 * kM * kE : 2 * kM * kDIM];
__device__ float g_proj[kM * kE];

struct Perms { int sp[kL]; int ra[kL]; int bd[kL]; };

// ---------------- helpers ----------------
__device__ __forceinline__ float softplusf(float v) {
    return fmaxf(v, 0.f) + log1pf(expf(-fabsf(v)));
}
__device__ __forceinline__ float siluf(float v) {
    return v / (1.f + expf(-v));
}
__device__ __forceinline__ uint32_t smem_to_u32(const void* p) {
    uint32_t a;
    asm("{ .reg .u64 t; cvta.to.shared.u64 t, %1; cvt.u32.u64 %0, t; }" : "=r"(a) : "l"(p));
    return a;
}

// ldmatrix x4 (four 8x8 b16 tiles == four 8x4 f32 tiles)
__device__ __forceinline__ void ldsm4(uint32_t* r, uint32_t addr) {
    asm volatile("ldmatrix.sync.aligned.m8n8.x4.shared.b16 {%0,%1,%2,%3}, [%4];"
        : "=r"(r[0]), "=r"(r[1]), "=r"(r[2]), "=r"(r[3]) : "r"(addr));
}
// m16n8k8 tf32 mma, accumulate in place
__device__ __forceinline__ void mma8(float* c, const uint32_t* a, const uint32_t* b) {
    asm volatile("mma.sync.aligned.m16n8k8.row.col.f32.tf32.tf32.f32 "
        "{%0,%1,%2,%3}, {%4,%5,%6,%7}, {%8,%9}, {%0,%1,%2,%3};"
        : "+f"(c[0]), "+f"(c[1]), "+f"(c[2]), "+f"(c[3])
        : "r"(a[0]), "r"(a[1]), "r"(a[2]), "r"(a[3]), "r"(b[0]), "r"(b[1]));
}

// ---------------- 3xTF32 mma.sync GEMM ----------------
// C[z] = A(MxK, lda) @ W(NxK)^T over k in [z*kChunk,(z+1)*kChunk)
// Block 128x128, BK=32. epi: 0 none, 1 +bias[n], 2 softplus(v+bias[n])
#define GSTRIDE 36
#define GEMM_SMEM (4 * 128 * GSTRIDE * 4)

__global__ __launch_bounds__(256) void mma_gemm_tf32(
    const float* __restrict__ A, int lda,
    const float* __restrict__ W,
    float* __restrict__ C,
    int M, int N, int K, int kChunk,
    const float* __restrict__ bias, int epi)
{
    extern __shared__ float sm[];
    float* sAh = sm;
    float* sAl = sm + 128 * GSTRIDE;
    float* sBh = sm + 2 * 128 * GSTRIDE;
    float* sBl = sm + 3 * 128 * GSTRIDE;

    const int tid = threadIdx.x;
    const int lane = tid & 31, wid = tid >> 5;
    const int wm = wid & 1, wn = wid >> 1;          // warp grid 2 x 4
    const int m0 = blockIdx.y * 128, n0 = blockIdx.x * 128;
    const int z = blockIdx.z, k0 = z * kChunk;
    float* Cz = C + (size_t)z * M * N;

    const uint32_t sbase = smem_to_u32(sm);
    const uint32_t aAh = sbase;
    const uint32_t aAl = sbase + 128 * GSTRIDE * 4;
    const uint32_t aBh = sbase + 2 * 128 * GSTRIDE * 4;
    const uint32_t aBl = sbase + 3 * 128 * GSTRIDE * 4;

    // ldmatrix per-thread address components
    const int q = lane >> 3, r = lane & 7;
    const int a_row = wm * 64 + ((q & 1) << 3) + r;   // + mt*16
    const int a_col = (q >> 1) << 2;                  // + ks*8
    const int b_row = wn * 32 + ((q >> 1) << 3) + r;  // + np*16
    const int b_col = (q & 1) << 2;                   // + ks*8

    float c[4][4][4];
    #pragma unroll
    for (int i = 0; i < 4; i++)
        #pragma unroll
        for (int j = 0; j < 4; j++)
            #pragma unroll
            for (int k = 0; k < 4; k++) c[i][j][k] = 0.f;

    const int nCh = kChunk / 32;
    for (int ch = 0; ch < nCh; ch++) {
        const int kc = k0 + ch * 32;
        // ---- global -> smem with hi/lo split ----
        #pragma unroll
        for (int it = 0; it < 4; it++) {
            int idx = tid + (it << 8);        // 0..1023
            int row = idx >> 3, qq = idx & 7;
            int so = row * GSTRIDE + qq * 4;
            {   // A
                float4 v = make_float4(0.f, 0.f, 0.f, 0.f);
                int gm = m0 + row;
                if (gm < M) v = *reinterpret_cast<const float4*>(&A[(size_t)gm * lda + kc + qq * 4]);
                float4 h, lo;
                h.x = __uint_as_float(__float_as_uint(v.x) & 0xFFFFE000u); lo.x = v.x - h.x;
                h.y = __uint_as_float(__float_as_uint(v.y) & 0xFFFFE000u); lo.y = v.y - h.y;
                h.z = __uint_as_float(__float_as_uint(v.z) & 0xFFFFE000u); lo.z = v.z - h.z;
                h.w = __uint_as_float(__float_as_uint(v.w) & 0xFFFFE000u); lo.w = v.w - h.w;
                *reinterpret_cast<float4*>(&sAh[so]) = h;
                *reinterpret_cast<float4*>(&sAl[so]) = lo;
            }
            {   // B
                float4 v = make_float4(0.f, 0.f, 0.f, 0.f);
                int gn = n0 + row;
                if (gn < N) v = *reinterpret_cast<const float4*>(&W[(size_t)gn * K + kc + qq * 4]);
                float4 h, lo;
                h.x = __uint_as_float(__float_as_uint(v.x) & 0xFFFFE000u); lo.x = v.x - h.x;
                h.y = __uint_as_float(__float_as_uint(v.y) & 0xFFFFE000u); lo.y = v.y - h.y;
                h.z = __uint_as_float(__float_as_uint(v.z) & 0xFFFFE000u); lo.z = v.z - h.z;
                h.w = __uint_as_float(__float_as_uint(v.w) & 0xFFFFE000u); lo.w = v.w - h.w;
                *reinterpret_cast<float4*>(&sBh[so]) = h;
                *reinterpret_cast<float4*>(&sBl[so]) = lo;
            }
        }
        __syncthreads();

        // ---- compute: 4 k-steps of k=8 ----
        #pragma unroll
        for (int ks = 0; ks < 4; ks++) {
            uint32_t ah[4][4], al[4][4], bh[2][4], bl[2][4];
            #pragma unroll
            for (int mt = 0; mt < 4; mt++) {
                uint32_t off = (uint32_t)(((a_row + mt * 16) * GSTRIDE + a_col + ks * 8) * 4);
                ldsm4(ah[mt], aAh + off);
                ldsm4(al[mt], aAl + off);
            }
            #pragma unroll
            for (int np = 0; np < 2; np++) {
                uint32_t off = (uint32_t)(((b_row + np * 16) * GSTRIDE + b_col + ks * 8) * 4);
                ldsm4(bh[np], aBh + off);
                ldsm4(bl[np], aBl + off);
            }
            #pragma unroll
            for (int mt = 0; mt < 4; mt++) {
                #pragma unroll
                for (int nt = 0; nt < 4; nt++) {
                    const uint32_t* bhp = &bh[nt >> 1][(nt & 1) << 1];
                    const uint32_t* blp = &bl[nt >> 1][(nt & 1) << 1];
                    mma8(c[mt][nt], ah[mt], bhp);   // hi*hi
                    mma8(c[mt][nt], ah[mt], blp);   // hi*lo
                    mma8(c[mt][nt], al[mt], bhp);   // lo*hi
                }
            }
        }
        __syncthreads();
    }

    // ---- epilogue ----
    const int g = lane >> 2, t = lane & 3;
    #pragma unroll
    for (int mt = 0; mt < 4; mt++) {
        #pragma unroll
        for (int nt = 0; nt < 4; nt++) {
            int gn = n0 + wn * 32 + nt * 8 + t * 2;
            if (gn >= N) continue;
            #pragma unroll
            for (int half = 0; half < 2; half++) {
                int gm = m0 + wm * 64 + mt * 16 + g + half * 8;
                if (gm >= M) continue;
                float v0 = c[mt][nt][half * 2 + 0];
                float v1 = c[mt][nt][half * 2 + 1];
                if (epi == 1) { v0 += bias[gn]; v1 += bias[gn + 1]; }
                else if (epi == 2) {
                    v0 = softplusf(v0 + bias[gn]);
                    v1 = softplusf(v1 + bias[gn + 1]);
                }
                Cz[(size_t)gm * N + gn]     = v0;
                Cz[(size_t)gm * N + gn + 1] = v1;
            }
        }
    }
}

// ---------------- block reduce ----------------
__device__ __forceinline__ float block_reduce_256(float v, float* red) {
    #pragma unroll
    for (int o = 16; o; o >>= 1) v += __shfl_xor_sync(0xffffffffu, v, o);
    if ((threadIdx.x & 31) == 0) red[threadIdx.x >> 5] = v;
    __syncthreads();
    float r = 0.f;
    if (threadIdx.x < 8) {
        r = red[threadIdx.x];
        #pragma unroll
        for (int o = 4; o; o >>= 1) r += __shfl_xor_sync(0xffu, r, o);
        if (threadIdx.x == 0) red[0] = r;
    }
    __syncthreads();
    r = red[0];
    __syncthreads();
    return r;
}

// ---------------- patch embedding ----------------
__global__ __launch_bounds__(256) void patch_embed_kernel(
    const float* __restrict__ x, const float* __restrict__ pw,
    const float* __restrict__ pb, const float* __restrict__ pos,
    const float* __restrict__ af, const float* __restrict__ aw,
    const float* __restrict__ ab, float* __restrict__ xe)
{
    __shared__ float patch[768];
    int blk = blockIdx.x;
    int b = blk / kL, l = blk % kL;
    int h = l / 14, w = l % 14;
    int tid = threadIdx.x;
    for (int k = tid; k < 768; k += 256) {
        int c = k >> 8, rem = k & 255, i = rem >> 4, j = rem & 15;
        patch[k] = x[(((size_t)b * 3 + c) * 224 + (h * 16 + i)) * 224 + (w * 16 + j)];
    }
    __syncthreads();
    float f0 = af[b*5+0], f1 = af[b*5+1], f2 = af[b*5+2], f3 = af[b*5+3], f4 = af[b*5+4];
    for (int e = tid; e < 768; e += 256) {
        float acc = pb[e];
        const float* wr = pw + (size_t)e * 768;
        #pragma unroll 8
        for (int k = 0; k < 768; k++) acc += patch[k] * wr[k];
        acc += pos[(size_t)l * 768 + e] + ab[e]
             + f0*aw[e*5+0] + f1*aw[e*5+1] + f2*aw[e*5+2] + f3*aw[e*5+3] + f4*aw[e*5+4];
        xe[((size_t)b * kL + l) * 768 + e] = acc;
    }
}

// ---------------- permutation concat ----------------
__global__ __launch_bounds__(256) void gather_kernel(
    const float* __restrict__ xe, float* __restrict__ xm, Perms P)
{
    int i = blockIdx.x * 256 + threadIdx.x;
    if (i >= kM * kDIM) return;
    int col = i % kDIM;
    int row = i / kDIM;
    int b = row / kL, t = row % kL;
    int c = col / kE, e = col % kE;
    int ts = (c == 0) ? P.sp[t] : (c == 1) ? P.ra[t] : (c == 2) ? P.bd[t] : t;
    xm[i] = xe[((size_t)(b * kL + ts)) * kE + e];
}

// ---------------- layernorm over rows ----------------
__global__ __launch_bounds__(256) void layernorm_rows(
    const float* __restrict__ in, float* __restrict__ out,
    const float* __restrict__ w, const float* __restrict__ b, int C)
{
    __shared__ float red[8];
    int row = blockIdx.x, tid = threadIdx.x;
    const float* xr = in + (size_t)row * C;
    float v[12];
    int cnt = C >> 8;
    float s = 0.f;
    for (int i = 0; i < cnt; i++) { v[i] = xr[tid + (i << 8)]; s += v[i]; }
    float mean = block_reduce_256(s, red) / (float)C;
    float q = 0.f;
    for (int i = 0; i < cnt; i++) { float d = v[i] - mean; q += d * d; }
    float var = block_reduce_256(q, red) / (float)C;
    float rs = rsqrtf(var + 1e-5f);
    float* o = out + (size_t)row * C;
    for (int i = 0; i < cnt; i++) {
        int c = tid + (i << 8);
        o[c] = (v[i] - mean) * rs * w[c] + b[c];
    }
}

// ---------------- split-K reduce (+epilogue) ----------------
__global__ __launch_bounds__(256) void reduce_splitk(
    const float* __restrict__ part, float* __restrict__ out,
    int MN, int N, int S, const float* __restrict__ extra, int epi)
{
    int i = blockIdx.x * 256 + threadIdx.x;
    if (i >= MN) return;
    float s = 0.f;
    for (int zz = 0; zz < S; zz++) s += part[(size_t)zz * MN + i];
    if (epi == 1)      s += extra[i % N];
    else if (epi == 2) s += extra[i];
    out[i] = s;
}

// ---------------- causal depthwise conv(4) + SiLU ----------------
__global__ __launch_bounds__(256) void conv_silu_kernel(
    const float* __restrict__ xr, const float* __restrict__ cw,
    const float* __restrict__ cb, float* __restrict__ xs)
{
    int i = blockIdx.x * 256 + threadIdx.x;
    if (i >= kM * kDIN) return;
    int d = i % kDIN;
    int row = i / kDIN;
    int b = row / kL, t = row % kL;
    float acc = cb[d];
    #pragma unroll
    for (int j = 0; j < 4; j++) {
        int tt = t - 3 + j;
        if (tt >= 0)
            acc += cw[d * 4 + j] * xr[((size_t)(b * kL + tt)) * kDIN2 + d];
    }
    xs[i] = siluf(acc);
}

// ---------------- selective scan ----------------
__global__ __launch_bounds__(128) void scan_kernel(
    const float* __restrict__ dt, const float* __restrict__ dbl,
    const float* __restrict__ xs, const float* __restrict__ xr,
    const float* __restrict__ alog, const float* __restrict__ dpar,
    float* __restrict__ y)
{
    int idx = blockIdx.x * 128 + threadIdx.x;
    int b = idx / kDIN, d = idx % kDIN;
    float A[kDST];
    #pragma unroll
    for (int n = 0; n < kDST; n++) A[n] = -expf(alog[(size_t)d * kDST + n]);
    float Dv = dpar[d];
    float st[kDST];
    #pragma unroll
    for (int n = 0; n < kDST; n++) st[n] = 0.f;

    for (int t = 0; t < kL; t++) {
        size_t row = (size_t)b * kL + t;
        float dtv = dt[row * kDIN + d];
        float xv  = xs[row * kDIN + d];
        const float* bc = dbl + row * kXPN + kDTR;
        float dtx = dtv * xv;
        float yv = 0.f;
        #pragma unroll
        for (int n = 0; n < kDST; n++) {
            st[n] = st[n] * __expf(dtv * A[n]) + dtx * __ldg(&bc[n]);
            yv += st[n] * __ldg(&bc[kDST + n]);
        }
        float r = xr[row * kDIN2 + kDIN + d];
        y[row * kDIN + d] = (yv + xv * Dv) * siluf(r);
    }
}

// ---------------- final token mean ----------------
__global__ void final_mean_kernel(const float* __restrict__ xp, float* __restrict__ out)
{
    int i = blockIdx.x * 256 + threadIdx.x;
    if (i >= kB * kE) return;
    int b = i / kE, e = i % kE;
    float s = 0.f;
    for (int t = 0; t < kL; t++) s += xp[((size_t)b * kL + t) * kE + e];
    out[i] = s * (1.0f / 196.0f);
}

// ---------------- host: permutations (bit-exact replica) ----------------
static void compute_perms(Perms& P)
{
    const int Hh = 14, Ww = 14, ch = 7, cw = 7;
    {
        bool seen[kL] = {false};
        int no = 0;
        for (int r = 0; r < 14; r++) {
            int n = (2 * r > 8) ? 2 * r : 8;
            double step = (2.0 * M_PI) / (double)n;
            for (int k = 0; k < n; k++) {
                double ang = (double)k * step;
                int h = (int)((double)ch + (double)r * cos(ang));
                int w = (int)((double)cw + (double)r * sin(ang));
                if (h >= 0 && h < Hh && w >= 0 && w < Ww) {
                    int i = h * Ww + w;
                    if (!seen[i]) { seen[i] = true; P.sp[no++] = i; }
                }
            }
        }
        for (int i = 0; i < kL; i++) if (!seen[i]) P.sp[no++] = i;
    }
    {
        struct Item { double d, a; int i; };
        Item items[kL];
        int c = 0;
        for (int h = 0; h < Hh; h++)
            for (int w = 0; w < Ww; w++) {
                double dh = h - ch, dw = w - cw;
                items[c].d = sqrt(dh * dh + dw * dw);
                items[c].a = atan2(dh, dw);
                items[c].i = h * Ww + w;
                c++;
            }
        std::stable_sort(items, items + kL, [](const Item& x, const Item& y) {
            if (x.d != y.d) return x.d > y.d;
            return x.a < y.a;
        });
        for (int i = 0; i < kL; i++) P.ra[i] = items[i].i;
    }
    {
        int nb = 0;
        for (int h = 0; h < Hh; h++)
            for (int w = 0; w < Ww; w++)
                if (h == 0 || h == Hh - 1 || w == 0 || w == Ww - 1)
                    P.bd[nb++] = h * Ww + w;
        for (int h = 0; h < Hh; h++)
            for (int w = 0; w < Ww; w++)
                if (!(h == 0 || h == Hh - 1 || w == 0 || w == Ww - 1))
                    P.bd[nb++] = h * Ww + w;
    }
}

// ---------------- launch ----------------
extern "C" void kernel_launch(void* const* d_in, const int* in_sizes, int n_in,
                              void* d_out, int out_size)
{
    (void)n_in; (void)out_size;
    const float* x       = (const float*)d_in[0];
    const float* abf     = (const float*)d_in[1];
    const float* patch_w = (const float*)d_in[2];
    const float* patch_b = (const float*)d_in[3];
    const float* pos     = (const float*)d_in[4];
    const float* abw     = (const float*)d_in[5];
    const float* abb     = (const float*)d_in[6];
    const float* ln_w    = (const float*)d_in[7];
    const float* ln_b    = (const float*)d_in[8];
    const float* inw     = (const float*)d_in[9];
    const float* convw   = (const float*)d_in[10];
    const float* convb   = (const float*)d_in[11];
    const float* xpw     = (const float*)d_in[12];
    const float* dtw     = (const float*)d_in[13];
    const float *dtb, *alog, *dpar, *outw, *projw, *projb, *normw, *normb;
    if (in_sizes[14] == 2 * kDIN) {
        dtb   = (const float*)d_in[14]; alog  = (const float*)d_in[15];
        dpar  = (const float*)d_in[16]; outw  = (const float*)d_in[17];
        projw = (const float*)d_in[18]; projb = (const float*)d_in[19];
        normw = (const float*)d_in[20]; normb = (const float*)d_in[21];
    } else {
        alog  = (const float*)d_in[14]; dpar  = (const float*)d_in[15];
        outw  = (const float*)d_in[16]; projw = (const float*)d_in[17];
        projb = (const float*)d_in[18]; normw = (const float*)d_in[19];
        normb = (const float*)d_in[20]; dtb   = (const float*)d_in[21];
    }

    float *xe, *xm, *xln, *xr, *xs, *dbl, *dt, *y, *part, *proj;
    cudaGetSymbolAddress((void**)&xe,   g_xe);
    cudaGetSymbolAddress((void**)&xm,   g_xm);
    cudaGetSymbolAddress((void**)&xln,  g_xln);
    cudaGetSymbolAddress((void**)&xr,   g_xr);
    cudaGetSymbolAddress((void**)&xs,   g_xs);
    cudaGetSymbolAddress((void**)&dbl,  g_dbl);
    cudaGetSymbolAddress((void**)&dt,   g_dt);
    cudaGetSymbolAddress((void**)&y,    g_y);
    cudaGetSymbolAddress((void**)&part, g_part);
    cudaGetSymbolAddress((void**)&proj, g_proj);

    cudaFuncSetAttribute(mma_gemm_tf32, cudaFuncAttributeMaxDynamicSharedMemorySize, GEMM_SMEM);

    auto gemm = [&](const float* A, int lda, const float* W, float* C,
                    int M, int N, int K, int S, const float* bias, int epi) {
        int kChunk = K / S;     // must be a multiple of 32
        dim3 grid((N + 127) / 128, (M + 127) / 128, S);
        mma_gemm_tf32<<<grid, 256, GEMM_SMEM>>>(A, lda, W, C, M, N, K, kChunk, bias, epi);
    };

    // --- patch embed + permutation concat ---
    patch_embed_kernel<<<kM, 256>>>(x, patch_w, patch_b, pos, abf, abw, abb, xe);
    Perms P;
    compute_perms(P);
    gather_kernel<<<(kM * kDIM) / 256, 256>>>(xe, xm, P);

    // --- mamba layers ---
    for (int l = 0; l < 2; l++) {
        layernorm_rows<<<kM, 256>>>(xm, xln, ln_w + l * kDIM, ln_b + l * kDIM, kDIM);
        // in_proj: (392,3072) @ (12288,3072)^T
        gemm(xln, kDIM, inw + (size_t)l * kDIN2 * kDIM, xr, kM, kDIN2, kDIM, 1, nullptr, 0);
        conv_silu_kernel<<<(kM * kDIN) / 256, 256>>>(xr, convw + (size_t)l * kDIN * 4,
                                                     convb + l * kDIN, xs);
        // x_proj: (392,6144) @ (224,6144)^T  split-K 16 (kChunk=384)
        gemm(xs, kDIN, xpw + (size_t)l * kXPN * kDIN, part, kM, kXPN, kDIN, 16, nullptr, 0);
        reduce_splitk<<<(kM * kXPN + 255) / 256, 256>>>(part, dbl, kM * kXPN, kXPN, 16, nullptr, 0);
        // dt_proj + softplus: (392, lda=224) K=192 @ (6144,192)^T
        gemm(dbl, kXPN, dtw + (size_t)l * kDIN * kDTR, dt, kM, kDIN, kDTR, 1, dtb + l * kDIN, 2);
        scan_kernel<<<(kB * kDIN) / 128, 128>>>(dt, dbl, xs, xr,
                                                alog + (size_t)l * kDIN * kDST,
                                                dpar + l * kDIN, y);
        // out_proj + residual: (392,6144) @ (3072,6144)^T  split-K 2
        gemm(y, kDIN, outw + (size_t)l * kDIM * kDIN, part, kM, kDIM, kDIN, 2, nullptr, 0);
        reduce_splitk<<<(kM * kDIM + 255) / 256, 256>>>(part, xm, kM * kDIM, kDIM, 2, xm, 2);
    }

    // --- final projection + LN + mean ---  split-K 6 (kChunk=512)
    gemm(xm, kDIM, projw, part, kM, kE, kDIM, 6, nullptr, 0);
    reduce_splitk<<<(kM * kE + 255) / 256, 256>>>(part, proj, kM * kE, kE, 6, projb, 1);
    layernorm_rows<<<kM, 256>>>(proj, proj, normw, normb, kE);
    final_mean_kernel<<<(kB * kE + 255) / 256, 256>>>(proj, (float*)d_out);
}

// round 10
// speedup vs baseline: 1.5983x; 1.1415x over previous
#include <cuda_runtime.h>
#include <cstdint>
#include <cmath>
#include <algorithm>

#ifndef M_PI
#define M_PI 3.14159265358979323846
#endif

// ---------------- constants ----------------
#define kB    2
#define kL    196
#define kE    768
#define kDIM  3072
#define kDIN  6144
#define kDIN2 12288
#define kDTR  192
#define kDST  16
#define kM    392            // kB*kL
#define kXPN  224            // kDTR + 2*kDST

// ---------------- device scratch ----------------
__device__ float g_xe  [kM * kE];
__device__ float g_xm  [kM * kDIM];
__device__ float g_xln [kM * kDIM];
__device__ float g_xr  [kM * kDIN2];
__device__ float g_xs  [kM * kDIN];
__device__ float g_dbl [kM * kXPN];
__device__ float g_dt  [kM * kDIN];
__device__ float g_y   [kM * kDIN];
__device__ float g_part[16 * kM * kXPN > 6 * kM * kE ? 16 * kM * kXPN : 6 * kM * kE > 2 * kM * kDIM ? 6 * kM * kE : 2 * kM * kDIM];
__device__ float g_proj[kM * kE];

struct Perms { int sp[kL]; int ra[kL]; int bd[kL]; };

// ---------------- helpers ----------------
__device__ __forceinline__ float softplusf(float v) {
    return fmaxf(v, 0.f) + log1pf(expf(-fabsf(v)));
}
__device__ __forceinline__ float siluf(float v) {
    return v / (1.f + expf(-v));
}
__device__ __forceinline__ uint32_t smem_to_u32(const void* p) {
    uint32_t a;
    asm("{ .reg .u64 t; cvta.to.shared.u64 t, %1; cvt.u32.u64 %0, t; }" : "=r"(a) : "l"(p));
    return a;
}
__device__ __forceinline__ void cp_async16(uint32_t dst, const void* src, int src_sz) {
    asm volatile("cp.async.cg.shared.global [%0], [%1], 16, %2;"
        :: "r"(dst), "l"(src), "r"(src_sz));
}
#define CP_COMMIT() asm volatile("cp.async.commit_group;" ::: "memory")
#define CP_WAIT0()  asm volatile("cp.async.wait_group 0;" ::: "memory")

// ldmatrix x4 (four 8x8 b16 tiles == four 8x4 f32 tiles)
__device__ __forceinline__ void ldsm4(uint32_t* r, uint32_t addr) {
    asm volatile("ldmatrix.sync.aligned.m8n8.x4.shared.b16 {%0,%1,%2,%3}, [%4];"
        : "=r"(r[0]), "=r"(r[1]), "=r"(r[2]), "=r"(r[3]) : "r"(addr));
}
// m16n8k8 tf32 mma, accumulate in place
__device__ __forceinline__ void mma8(float* c, const uint32_t* a, const uint32_t* b) {
    asm volatile("mma.sync.aligned.m16n8k8.row.col.f32.tf32.tf32.f32 "
        "{%0,%1,%2,%3}, {%4,%5,%6,%7}, {%8,%9}, {%0,%1,%2,%3};"
        : "+f"(c[0]), "+f"(c[1]), "+f"(c[2]), "+f"(c[3])
        : "r"(a[0]), "r"(a[1]), "r"(a[2]), "r"(a[3]), "r"(b[0]), "r"(b[1]));
}

// ---------------- 3xTF32 mma.sync GEMM, cp.async double-buffered ----------------
// C[z] = A(MxK, lda) @ W(NxK)^T over k in [z*kChunk,(z+1)*kChunk)
// Block 128x128, BK=32. Raw fp32 tiles in smem; hi/lo split on fragment regs.
// epi: 0 none, 1 +bias[n], 2 softplus(v+bias[n])
#define GSTRIDE 36
#define TILEB   (128 * GSTRIDE * 4)          // one A or B tile, bytes (18432)
#define BUFB    (2 * TILEB)                  // A+B per stage (36864)
#define GEMM_SMEM (2 * BUFB)                 // double-buffered (73728)

__global__ __launch_bounds__(256, 2) void mma_gemm_tf32(
    const float* __restrict__ A, int lda,
    const float* __restrict__ W,
    float* __restrict__ C,
    int M, int N, int K, int kChunk,
    const float* __restrict__ bias, int epi)
{
    extern __shared__ float sm[];
    const int tid = threadIdx.x;
    const int lane = tid & 31, wid = tid >> 5;
    const int wm = wid & 1, wn = wid >> 1;          // warp grid 2 x 4
    const int m0 = blockIdx.y * 128, n0 = blockIdx.x * 128;
    const int z = blockIdx.z, k0 = z * kChunk;
    float* Cz = C + (size_t)z * M * N;
    const uint32_t sbase = smem_to_u32(sm);

    // ldmatrix per-thread address components
    const int q = lane >> 3, r = lane & 7;
    const int a_row = wm * 64 + ((q & 1) << 3) + r;   // + mt*16
    const int a_col = (q >> 1) << 2;                  // + ks*8
    const int b_row = wn * 32 + ((q >> 1) << 3) + r;  // + np*16
    const int b_col = (q & 1) << 2;                   // + ks*8

    float c[4][4][4];
    #pragma unroll
    for (int i = 0; i < 4; i++)
        #pragma unroll
        for (int j = 0; j < 4; j++)
            #pragma unroll
            for (int k = 0; k < 4; k++) c[i][j][k] = 0.f;

    auto issue_loads = [&](int kc, int stage) {
        #pragma unroll
        for (int it = 0; it < 4; it++) {
            int idx = tid + (it << 8);            // 0..1023
            int row = idx >> 3, qq = idx & 7;
            uint32_t so = sbase + stage * BUFB + (uint32_t)(row * GSTRIDE + qq * 4) * 4;
            int gm = m0 + row;
            cp_async16(so, A + (size_t)gm * lda + kc + qq * 4, gm < M ? 16 : 0);
            int gn = n0 + row;
            cp_async16(so + TILEB, W + (size_t)gn * K + kc + qq * 4, gn < N ? 16 : 0);
        }
        CP_COMMIT();
    };

    const int nCh = kChunk / 32;
    issue_loads(k0, 0);
    CP_WAIT0();
    __syncthreads();

    int p = 0;
    for (int ch = 0; ch < nCh; ch++) {
        if (ch + 1 < nCh) issue_loads(k0 + (ch + 1) * 32, p ^ 1);

        const uint32_t aA = sbase + p * BUFB;
        const uint32_t aB = aA + TILEB;
        #pragma unroll
        for (int ks = 0; ks < 4; ks++) {
            uint32_t ah[4][4], al[4][4], bh[2][4], bl[2][4];
            #pragma unroll
            for (int mt = 0; mt < 4; mt++) {
                uint32_t t4[4];
                ldsm4(t4, aA + (uint32_t)(((a_row + mt * 16) * GSTRIDE + a_col + ks * 8) * 4));
                #pragma unroll
                for (int j = 0; j < 4; j++) {
                    uint32_t h = t4[j] & 0xFFFFE000u;
                    ah[mt][j] = h;
                    al[mt][j] = __float_as_uint(__uint_as_float(t4[j]) - __uint_as_float(h));
                }
            }
            #pragma unroll
            for (int np = 0; np < 2; np++) {
                uint32_t t4[4];
                ldsm4(t4, aB + (uint32_t)(((b_row + np * 16) * GSTRIDE + b_col + ks * 8) * 4));
                #pragma unroll
                for (int j = 0; j < 4; j++) {
                    uint32_t h = t4[j] & 0xFFFFE000u;
                    bh[np][j] = h;
                    bl[np][j] = __float_as_uint(__uint_as_float(t4[j]) - __uint_as_float(h));
                }
            }
            #pragma unroll
            for (int mt = 0; mt < 4; mt++) {
                #pragma unroll
                for (int nt = 0; nt < 4; nt++) {
                    const uint32_t* bhp = &bh[nt >> 1][(nt & 1) << 1];
                    const uint32_t* blp = &bl[nt >> 1][(nt & 1) << 1];
                    mma8(c[mt][nt], ah[mt], bhp);   // hi*hi
                    mma8(c[mt][nt], ah[mt], blp);   // hi*lo
                    mma8(c[mt][nt], al[mt], bhp);   // lo*hi
                }
            }
        }
        CP_WAIT0();
        __syncthreads();
        p ^= 1;
    }

    // ---- epilogue ----
    const int g = lane >> 2, t = lane & 3;
    #pragma unroll
    for (int mt = 0; mt < 4; mt++) {
        #pragma unroll
        for (int nt = 0; nt < 4; nt++) {
            int gn = n0 + wn * 32 + nt * 8 + t * 2;
            if (gn >= N) continue;
            #pragma unroll
            for (int half = 0; half < 2; half++) {
                int gm = m0 + wm * 64 + mt * 16 + g + half * 8;
                if (gm >= M) continue;
                float v0 = c[mt][nt][half * 2 + 0];
                float v1 = c[mt][nt][half * 2 + 1];
                if (epi == 1) { v0 += bias[gn]; v1 += bias[gn + 1]; }
                else if (epi == 2) {
                    v0 = softplusf(v0 + bias[gn]);
                    v1 = softplusf(v1 + bias[gn + 1]);
                }
                Cz[(size_t)gm * N + gn]     = v0;
                Cz[(size_t)gm * N + gn + 1] = v1;
            }
        }
    }
}

// ---------------- block reduce ----------------
__device__ __forceinline__ float block_reduce_256(float v, float* red) {
    #pragma unroll
    for (int o = 16; o; o >>= 1) v += __shfl_xor_sync(0xffffffffu, v, o);
    if ((threadIdx.x & 31) == 0) red[threadIdx.x >> 5] = v;
    __syncthreads();
    float r = 0.f;
    if (threadIdx.x < 8) {
        r = red[threadIdx.x];
        #pragma unroll
        for (int o = 4; o; o >>= 1) r += __shfl_xor_sync(0xffu, r, o);
        if (threadIdx.x == 0) red[0] = r;
    }
    __syncthreads();
    r = red[0];
    __syncthreads();
    return r;
}

// ---------------- patch embedding ----------------
__global__ __launch_bounds__(256) void patch_embed_kernel(
    const float* __restrict__ x, const float* __restrict__ pw,
    const float* __restrict__ pb, const float* __restrict__ pos,
    const float* __restrict__ af, const float* __restrict__ aw,
    const float* __restrict__ ab, float* __restrict__ xe)
{
    __shared__ float patch[768];
    int blk = blockIdx.x;
    int b = blk / kL, l = blk % kL;
    int h = l / 14, w = l % 14;
    int tid = threadIdx.x;
    for (int k = tid; k < 768; k += 256) {
        int c = k >> 8, rem = k & 255, i = rem >> 4, j = rem & 15;
        patch[k] = x[(((size_t)b * 3 + c) * 224 + (h * 16 + i)) * 224 + (w * 16 + j)];
    }
    __syncthreads();
    float f0 = af[b*5+0], f1 = af[b*5+1], f2 = af[b*5+2], f3 = af[b*5+3], f4 = af[b*5+4];
    for (int e = tid; e < 768; e += 256) {
        float acc = pb[e];
        const float* wr = pw + (size_t)e * 768;
        #pragma unroll 8
        for (int k = 0; k < 768; k++) acc += patch[k] * wr[k];
        acc += pos[(size_t)l * 768 + e] + ab[e]
             + f0*aw[e*5+0] + f1*aw[e*5+1] + f2*aw[e*5+2] + f3*aw[e*5+3] + f4*aw[e*5+4];
        xe[((size_t)b * kL + l) * 768 + e] = acc;
    }
}

// ---------------- permutation concat ----------------
__global__ __launch_bounds__(256) void gather_kernel(
    const float* __restrict__ xe, float* __restrict__ xm, Perms P)
{
    int i = blockIdx.x * 256 + threadIdx.x;
    if (i >= kM * kDIM) return;
    int col = i % kDIM;
    int row = i / kDIM;
    int b = row / kL, t = row % kL;
    int c = col / kE, e = col % kE;
    int ts = (c == 0) ? P.sp[t] : (c == 1) ? P.ra[t] : (c == 2) ? P.bd[t] : t;
    xm[i] = xe[((size_t)(b * kL + ts)) * kE + e];
}

// ---------------- layernorm over rows ----------------
__global__ __launch_bounds__(256) void layernorm_rows(
    const float* __restrict__ in, float* __restrict__ out,
    const float* __restrict__ w, const float* __restrict__ b, int C)
{
    __shared__ float red[8];
    int row = blockIdx.x, tid = threadIdx.x;
    const float* xr = in + (size_t)row * C;
    float v[12];
    int cnt = C >> 8;
    float s = 0.f;
    for (int i = 0; i < cnt; i++) { v[i] = xr[tid + (i << 8)]; s += v[i]; }
    float mean = block_reduce_256(s, red) / (float)C;
    float q = 0.f;
    for (int i = 0; i < cnt; i++) { float d = v[i] - mean; q += d * d; }
    float var = block_reduce_256(q, red) / (float)C;
    float rs = rsqrtf(var + 1e-5f);
    float* o = out + (size_t)row * C;
    for (int i = 0; i < cnt; i++) {
        int c = tid + (i << 8);
        o[c] = (v[i] - mean) * rs * w[c] + b[c];
    }
}

// ---------------- split-K reduce (+epilogue) ----------------
__global__ __launch_bounds__(256) void reduce_splitk(
    const float* __restrict__ part, float* __restrict__ out,
    int MN, int N, int S, const float* __restrict__ extra, int epi)
{
    int i = blockIdx.x * 256 + threadIdx.x;
    if (i >= MN) return;
    float s = 0.f;
    for (int zz = 0; zz < S; zz++) s += part[(size_t)zz * MN + i];
    if (epi == 1)      s += extra[i % N];
    else if (epi == 2) s += extra[i];
    out[i] = s;
}

// ---------------- causal depthwise conv(4) + SiLU ----------------
__global__ __launch_bounds__(256) void conv_silu_kernel(
    const float* __restrict__ xr, const float* __restrict__ cw,
    const float* __restrict__ cb, float* __restrict__ xs)
{
    int i = blockIdx.x * 256 + threadIdx.x;
    if (i >= kM * kDIN) return;
    int d = i % kDIN;
    int row = i / kDIN;
    int b = row / kL, t = row % kL;
    float acc = cb[d];
    #pragma unroll
    for (int j = 0; j < 4; j++) {
        int tt = t - 3 + j;
        if (tt >= 0)
            acc += cw[d * 4 + j] * xr[((size_t)(b * kL + tt)) * kDIN2 + d];
    }
    xs[i] = siluf(acc);
}

// ---------------- selective scan: 16 lanes per (b,d), 2 channels per warp ----------------
__global__ __launch_bounds__(256) void scan_kernel(
    const float* __restrict__ dt, const float* __restrict__ dbl,
    const float* __restrict__ xs, const float* __restrict__ xr,
    const float* __restrict__ alog, const float* __restrict__ dpar,
    float* __restrict__ y)
{
    int gw = (blockIdx.x * 256 + threadIdx.x) >> 5;   // global warp 0..6143
    int lane = threadIdx.x & 31;
    int half = lane >> 4, n = lane & 15;
    int pair = gw * 2 + half;                          // 0..kB*kDIN-1
    int b = pair / kDIN, d = pair % kDIN;

    float An = -expf(alog[(size_t)d * kDST + n]);
    float Dv = dpar[d];
    float st = 0.f;

    for (int t = 0; t < kL; t++) {
        size_t row = (size_t)b * kL + t;
        float dtv = __ldg(&dt[row * kDIN + d]);
        float xv  = __ldg(&xs[row * kDIN + d]);
        const float* bc = dbl + row * kXPN + kDTR;
        float Bn = __ldg(&bc[n]);
        float Cn = __ldg(&bc[kDST + n]);
        st = st * __expf(dtv * An) + dtv * xv * Bn;
        float cv = st * Cn;
        cv += __shfl_xor_sync(0xffffffffu, cv, 8);
        cv += __shfl_xor_sync(0xffffffffu, cv, 4);
        cv += __shfl_xor_sync(0xffffffffu, cv, 2);
        cv += __shfl_xor_sync(0xffffffffu, cv, 1);
        if (n == 0) {
            float rg = xr[row * kDIN2 + kDIN + d];
            y[row * kDIN + d] = (cv + xv * Dv) * siluf(rg);
        }
    }
}

// ---------------- final token mean ----------------
__global__ void final_mean_kernel(const float* __restrict__ xp, float* __restrict__ out)
{
    int i = blockIdx.x * 256 + threadIdx.x;
    if (i >= kB * kE) return;
    int b = i / kE, e = i % kE;
    float s = 0.f;
    for (int t = 0; t < kL; t++) s += xp[((size_t)b * kL + t) * kE + e];
    out[i] = s * (1.0f / 196.0f);
}

// ---------------- host: permutations (bit-exact replica) ----------------
static void compute_perms(Perms& P)
{
    const int Hh = 14, Ww = 14, ch = 7, cw = 7;
    {
        bool seen[kL] = {false};
        int no = 0;
        for (int r = 0; r < 14; r++) {
            int n = (2 * r > 8) ? 2 * r : 8;
            double step = (2.0 * M_PI) / (double)n;
            for (int k = 0; k < n; k++) {
                double ang = (double)k * step;
                int h = (int)((double)ch + (double)r * cos(ang));
                int w = (int)((double)cw + (double)r * sin(ang));
                if (h >= 0 && h < Hh && w >= 0 && w < Ww) {
                    int i = h * Ww + w;
                    if (!seen[i]) { seen[i] = true; P.sp[no++] = i; }
                }
            }
        }
        for (int i = 0; i < kL; i++) if (!seen[i]) P.sp[no++] = i;
    }
    {
        struct Item { double d, a; int i; };
        Item items[kL];
        int c = 0;
        for (int h = 0; h < Hh; h++)
            for (int w = 0; w < Ww; w++) {
                double dh = h - ch, dw = w - cw;
                items[c].d = sqrt(dh * dh + dw * dw);
                items[c].a = atan2(dh, dw);
                items[c].i = h * Ww + w;
                c++;
            }
        std::stable_sort(items, items + kL, [](const Item& x, const Item& y) {
            if (x.d != y.d) return x.d > y.d;
            return x.a < y.a;
        });
        for (int i = 0; i < kL; i++) P.ra[i] = items[i].i;
    }
    {
        int nb = 0;
        for (int h = 0; h < Hh; h++)
            for (int w = 0; w < Ww; w++)
                if (h == 0 || h == Hh - 1 || w == 0 || w == Ww - 1)
                    P.bd[nb++] = h * Ww + w;
        for (int h = 0; h < Hh; h++)
            for (int w = 0; w < Ww; w++)
                if (!(h == 0 || h == Hh - 1 || w == 0 || w == Ww - 1))
                    P.bd[nb++] = h * Ww + w;
    }
}

// ---------------- launch ----------------
extern "C" void kernel_launch(void* const* d_in, const int* in_sizes, int n_in,
                              void* d_out, int out_size)
{
    (void)n_in; (void)out_size;
    const float* x       = (const float*)d_in[0];
    const float* abf     = (const float*)d_in[1];
    const float* patch_w = (const float*)d_in[2];
    const float* patch_b = (const float*)d_in[3];
    const float* pos     = (const float*)d_in[4];
    const float* abw     = (const float*)d_in[5];
    const float* abb     = (const float*)d_in[6];
    const float* ln_w    = (const float*)d_in[7];
    const float* ln_b    = (const float*)d_in[8];
    const float* inw     = (const float*)d_in[9];
    const float* convw   = (const float*)d_in[10];
    const float* convb   = (const float*)d_in[11];
    const float* xpw     = (const float*)d_in[12];
    const float* dtw     = (const float*)d_in[13];
    const float *dtb, *alog, *dpar, *outw, *projw, *projb, *normw, *normb;
    if (in_sizes[14] == 2 * kDIN) {
        dtb   = (const float*)d_in[14]; alog  = (const float*)d_in[15];
        dpar  = (const float*)d_in[16]; outw  = (const float*)d_in[17];
        projw = (const float*)d_in[18]; projb = (const float*)d_in[19];
        normw = (const float*)d_in[20]; normb = (const float*)d_in[21];
    } else {
        alog  = (const float*)d_in[14]; dpar  = (const float*)d_in[15];
        outw  = (const float*)d_in[16]; projw = (const float*)d_in[17];
        projb = (const float*)d_in[18]; normw = (const float*)d_in[19];
        normb = (const float*)d_in[20]; dtb   = (const float*)d_in[21];
    }

    float *xe, *xm, *xln, *xr, *xs, *dbl, *dt, *y, *part, *proj;
    cudaGetSymbolAddress((void**)&xe,   g_xe);
    cudaGetSymbolAddress((void**)&xm,   g_xm);
    cudaGetSymbolAddress((void**)&xln,  g_xln);
    cudaGetSymbolAddress((void**)&xr,   g_xr);
    cudaGetSymbolAddress((void**)&xs,   g_xs);
    cudaGetSymbolAddress((void**)&dbl,  g_dbl);
    cudaGetSymbolAddress((void**)&dt,   g_dt);
    cudaGetSymbolAddress((void**)&y,    g_y);
    cudaGetSymbolAddress((void**)&part, g_part);
    cudaGetSymbolAddress((void**)&proj, g_proj);

    cudaFuncSetAttribute(mma_gemm_tf32, cudaFuncAttributeMaxDynamicSharedMemorySize, GEMM_SMEM);

    auto gemm = [&](const float* A, int lda, const float* W, float* C,
                    int M, int N, int K, int S, const float* bias, int epi) {
        int kChunk = K / S;     // must be a multiple of 32
        dim3 grid((N + 127) / 128, (M + 127) / 128, S);
        mma_gemm_tf32<<<grid, 256, GEMM_SMEM>>>(A, lda, W, C, M, N, K, kChunk, bias, epi);
    };

    // --- patch embed + permutation concat ---
    patch_embed_kernel<<<kM, 256>>>(x, patch_w, patch_b, pos, abf, abw, abb, xe);
    Perms P;
    compute_perms(P);
    gather_kernel<<<(kM * kDIM) / 256, 256>>>(xe, xm, P);

    // --- mamba layers ---
    for (int l = 0; l < 2; l++) {
        layernorm_rows<<<kM, 256>>>(xm, xln, ln_w + l * kDIM, ln_b + l * kDIM, kDIM);
        // in_proj: (392,3072) @ (12288,3072)^T
        gemm(xln, kDIM, inw + (size_t)l * kDIN2 * kDIM, xr, kM, kDIN2, kDIM, 1, nullptr, 0);
        conv_silu_kernel<<<(kM * kDIN) / 256, 256>>>(xr, convw + (size_t)l * kDIN * 4,
                                                     convb + l * kDIN, xs);
        // x_proj: (392,6144) @ (224,6144)^T  split-K 16 (kChunk=384)
        gemm(xs, kDIN, xpw + (size_t)l * kXPN * kDIN, part, kM, kXPN, kDIN, 16, nullptr, 0);
        reduce_splitk<<<(kM * kXPN + 255) / 256, 256>>>(part, dbl, kM * kXPN, kXPN, 16, nullptr, 0);
        // dt_proj + softplus: (392, lda=224) K=192 @ (6144,192)^T
        gemm(dbl, kXPN, dtw + (size_t)l * kDIN * kDTR, dt, kM, kDIN, kDTR, 1, dtb + l * kDIN, 2);
        // selective scan + gating: 6144 warps
        scan_kernel<<<(kB * kDIN / 2) / 8, 256>>>(dt, dbl, xs, xr,
                                                  alog + (size_t)l * kDIN * kDST,
                                                  dpar + l * kDIN, y);
        // out_proj + residual: (392,6144) @ (3072,6144)^T  split-K 2
        gemm(y, kDIN, outw + (size_t)l * kDIM * kDIN, part, kM, kDIM, kDIN, 2, nullptr, 0);
        reduce_splitk<<<(kM * kDIM + 255) / 256, 256>>>(part, xm, kM * kDIM, kDIM, 2, xm, 2);
    }

    // --- final projection + LN + mean ---  split-K 6 (kChunk=512)
    gemm(xm, kDIM, projw, part, kM, kE, kDIM, 6, nullptr, 0);
    reduce_splitk<<<(kM * kE + 255) / 256, 256>>>(part, proj, kM * kE, kE, 6, projb, 1);
    layernorm_rows<<<kM, 256>>>(proj, proj, normw, normb, kE);
    final_mean_kernel<<<(kB * kE + 255) / 256, 256>>>(proj, (float*)d_out);
}